// round 13
// baseline (speedup 1.0000x reference)
#include <cuda_runtime.h>

#define IMG_H 512
#define IMG_W 512
#define TX 32
#define TY 32
#define HALO 5
#define IN_W 42              // TX + 2*HALO
#define IN_H 42              // TY + 2*HALO
#define SP 43                // sxy row stride in float2 slots (43 mod 16 = 11 -> conflict-free)
#define HP 33                // H row stride in float4 slots (see bank audit in comments)
#define NT 256

#define C1V 1.0e-4f
#define C2V 9.0e-4f
#define EPSV 1.0e-8f

// Normalized 1D Gaussian, sigma=1.5, window 11 (symmetric). Compile-time
// constants -> FFMA with immediate multiplier (rt_SMSP=1 on sm_10x).
__device__ constexpr float GW[11] = {
    0.00102838f, 0.00759876f, 0.03600077f, 0.10936069f, 0.21300553f,
    0.26601172f,
    0.21300553f, 0.10936069f, 0.03600077f, 0.00759876f, 0.00102838f
};

__global__ void zero_out_kernel(float* out) { out[0] = 0.0f; }

__global__ __launch_bounds__(NT, 5) void ssim_kernel(
    const float* __restrict__ x, const float* __restrict__ y,
    float* __restrict__ out, float inv_n)
{
    // Sum/difference transform: convolve s=x+y, d=x-y -> 4 maps.
    // H maps interleaved as float4 (Hs, Hd, Hss, Hdd).
    __shared__ float2 sxy[IN_H * SP];    // (s, d)               14.4 KB
    __shared__ float4 Hmap[IN_H * HP];   // (Hs, Hd, Hss, Hdd)   22.2 KB
    __shared__ float  red[8];

    const int tid = threadIdx.x;
    const int x0 = blockIdx.x * TX - HALO;
    const int y0 = blockIdx.y * TY - HALO;
    const size_t imgoff = (size_t)blockIdx.z * (IMG_H * IMG_W);
    const float* xb = x + imgoff;
    const float* yb = y + imgoff;

    // ---- Phase 1: segment remap. Unit = 7 contiguous cols of one row.
    // 252 units (42 rows x 6 segments); one div-by-6 replaces seven
    // div-by-42 chains; loads/stores use immediate offsets off 2 bases.
    const bool interior = (x0 >= 0) & (y0 >= 0) &
                          (x0 + IN_W <= IMG_W) & (y0 + IN_H <= IMG_H);
    if (tid < 252) {
        const int r  = tid / 6;
        const int c0 = (tid - r * 6) * 7;       // 0,7,14,21,28,35
        float2* so = sxy + r * SP + c0;
        if (interior) {
            const float* px = xb + (y0 + r) * IMG_W + (x0 + c0);
            const float* py = yb + (y0 + r) * IMG_W + (x0 + c0);
            #pragma unroll
            for (int i = 0; i < 7; i++) {
                float xv = __ldg(px + i);
                float yv = __ldg(py + i);
                so[i] = make_float2(xv + yv, xv - yv);
            }
        } else {
            const int gy = y0 + r;
            const bool rowok = (gy >= 0) & (gy < IMG_H);
            const float* px = xb + gy * IMG_W + (x0 + c0);
            const float* py = yb + gy * IMG_W + (x0 + c0);
            #pragma unroll
            for (int i = 0; i < 7; i++) {
                const int gx = x0 + c0 + i;
                float sv = 0.0f, dv = 0.0f;
                if (rowok && gx >= 0 && gx < IMG_W) {
                    float xv = __ldg(px + i);
                    float yv = __ldg(py + i);
                    sv = xv + yv;
                    dv = xv - yv;
                }
                so[i] = make_float2(sv, dv);
            }
        }
    }
    __syncthreads();

    // ---- Phase 2: horizontal pass, FUSED (single load stream, 4 maps) ----
    // 168 units of 8 output cols; each pin[i] loaded exactly once.
    // Store bank audit (STS.128, 8-lane wavefronts = consecutive rows):
    // bank group = 4*((33*row + col) mod 8) -> distinct over 8 rows.
    if (tid < IN_H * 4) {
        const int cg  = tid / IN_H;          // 0..3 (8-col groups)
        const int row = tid - cg * IN_H;     // 0..41
        const float2* pin = sxy + row * SP + cg * 8;
        float as[8], ad[8], as2[8], ad2[8];
        #pragma unroll
        for (int i = 0; i < 18; i++) {
            float2 v = pin[i];
            float ss = v.x * v.x;
            float dd = v.y * v.y;
            #pragma unroll
            for (int k = 0; k < 8; k++) {
                const int d = i - k;
                if (d == 0) {                 // first tap: mul-init (no MOV 0)
                    as[k]  = v.x * GW[0];
                    ad[k]  = v.y * GW[0];
                    as2[k] = ss  * GW[0];
                    ad2[k] = dd  * GW[0];
                } else if (d > 0 && d <= 10) {
                    const float w = GW[d];
                    as[k]  = fmaf(v.x, w, as[k]);
                    ad[k]  = fmaf(v.y, w, ad[k]);
                    as2[k] = fmaf(ss,  w, as2[k]);
                    ad2[k] = fmaf(dd,  w, ad2[k]);
                }
            }
        }
        const int hb = row * HP + cg * 8;
        #pragma unroll
        for (int k = 0; k < 8; k++)
            Hmap[hb + k] = make_float4(as[k], ad[k], as2[k], ad2[k]);
    }
    __syncthreads();

    // ---- Phase 3: vertical pass + SSIM, 4 rows per thread ----
    // Load bank audit (LDS.128): lane c -> word 4c, conflict-free per wavefront.
    const int c     = tid & 31;
    const int rbase = (tid >> 5) * 4;
    float ms[4], md[4], mss[4], mdd[4];
    const float4* p = Hmap + rbase * HP + c;
    #pragma unroll
    for (int j = 0; j < 14; j++) {
        float4 h = p[j * HP];
        #pragma unroll
        for (int k = 0; k < 4; k++) {
            const int d = j - k;
            if (d == 0) {
                ms[k]  = h.x * GW[0];
                md[k]  = h.y * GW[0];
                mss[k] = h.z * GW[0];
                mdd[k] = h.w * GW[0];
            } else if (d > 0 && d <= 10) {
                const float w = GW[d];
                ms[k]  = fmaf(h.x, w, ms[k]);
                md[k]  = fmaf(h.y, w, md[k]);
                mss[k] = fmaf(h.z, w, mss[k]);
                mdd[k] = fmaf(h.w, w, mdd[k]);
            }
        }
    }

    // SSIM in sum/diff-native form:
    //   a = mus^2-mud^2 (=4 mux*muy)      b = mus^2+mud^2 (=2(mux^2+muy^2))
    //   e = Ess-Edd     (=4 E[xy])        f = Ess+Edd     (=2(E[x^2]+E[y^2]))
    float lsum = 0.0f;
    #pragma unroll
    for (int k = 0; k < 4; k++) {
        float mus = ms[k],  mud = md[k];
        float a = fmaf(mus, mus, -(mud * mud));
        float b = fmaf(mus, mus,  (mud * mud));
        float e = mss[k] - mdd[k];
        float f = mss[k] + mdd[k];
        float n   = fmaf(0.5f, a, C1V) * fmaf(0.5f, e - a, C2V);
        float den = fmaf(0.5f, b, C1V) * fmaf(0.5f, f - b, C2V) + EPSV;
        float v = fmaf(__fdividef(n, den), 0.5f, 0.5f);
        v = fminf(fmaxf(v, 0.0f), 1.0f);
        lsum += v;
    }

    // ---- Reduction: warp shuffle -> smem -> block -> atomic ----
    #pragma unroll
    for (int off = 16; off > 0; off >>= 1)
        lsum += __shfl_xor_sync(0xFFFFFFFFu, lsum, off);
    if ((tid & 31) == 0) red[tid >> 5] = lsum;
    __syncthreads();
    if (tid == 0) {
        float t = 0.0f;
        #pragma unroll
        for (int w = 0; w < 8; w++) t += red[w];
        atomicAdd(out, t * inv_n);
    }
}

extern "C" void kernel_launch(void* const* d_in, const int* in_sizes, int n_in,
                              void* d_out, int out_size)
{
    const float* x = (const float*)d_in[0];
    const float* y = (const float*)d_in[1];
    float* out = (float*)d_out;

    zero_out_kernel<<<1, 1>>>(out);

    dim3 grid(IMG_W / TX, IMG_H / TY, 16 * 3);   // 16 x 16 x 48
    const float inv_n = 1.0f / (float)(16 * 3 * IMG_H * IMG_W);
    ssim_kernel<<<grid, NT>>>(x, y, out, inv_n);
}

// round 14
// speedup vs baseline: 1.1461x; 1.1461x over previous
#include <cuda_runtime.h>

#define IMG_H 512
#define IMG_W 512
#define TX 32
#define TY 32
#define HALO 5
#define IN_W 42              // TX + 2*HALO
#define IN_H 42              // TY + 2*HALO
#define SP 43                // sxy row stride in float2 slots (43 mod 16 = 11 -> conflict-free)
#define HP 33                // H row stride in float4 slots (see bank audit in comments)
#define NT 256

#define C1V 1.0e-4f
#define C2V 9.0e-4f
#define EPSV 1.0e-8f

// Normalized 1D Gaussian, sigma=1.5, window 11 (symmetric). Compile-time
// constants -> FFMA with immediate multiplier (rt_SMSP=1 on sm_10x).
__device__ constexpr float GW[11] = {
    0.00102838f, 0.00759876f, 0.03600077f, 0.10936069f, 0.21300553f,
    0.26601172f,
    0.21300553f, 0.10936069f, 0.03600077f, 0.00759876f, 0.00102838f
};

__global__ void zero_out_kernel(float* out) { out[0] = 0.0f; }

__global__ __launch_bounds__(NT, 5) void ssim_kernel(
    const float* __restrict__ x, const float* __restrict__ y,
    float* __restrict__ out, float inv_n)
{
    // Sum/difference transform: convolve s=x+y, d=x-y -> 4 maps.
    // H maps interleaved as float4 (Hs, Hd, Hss, Hdd).
    __shared__ float2 sxy[IN_H * SP];    // (s, d)               14.4 KB
    __shared__ float4 Hmap[IN_H * HP];   // (Hs, Hd, Hss, Hdd)   22.2 KB
    __shared__ float  red[8];

    const int tid = threadIdx.x;
    const int x0 = blockIdx.x * TX - HALO;
    const int y0 = blockIdx.y * TY - HALO;
    const size_t imgoff = (size_t)blockIdx.z * (IMG_H * IMG_W);
    const float* xb = x + imgoff;
    const float* yb = y + imgoff;

    // ---- Phase 1: COALESCED grid-stride load (proven pattern from the
    // 88.5us champion), with incremental (r,c) bookkeeping instead of a
    // div-by-42 chain per iteration. Addresses and warp access pattern are
    // IDENTICAL to the champion: lanes hit consecutive columns -> 1-2
    // 128B lines per LDG. Step +256 = +6 rows +4 cols (256 = 6*42 + 4).
    const bool interior = (x0 >= 0) & (y0 >= 0) &
                          (x0 + IN_W <= IMG_W) & (y0 + IN_H <= IMG_H);
    {
        int r = tid / IN_W;          // one division total
        int c = tid - r * IN_W;
        if (interior) {
            #pragma unroll
            for (int it = 0; it < 7; it++) {
                if (r < IN_H) {      // == (idx < 1764)
                    int g = (y0 + r) * IMG_W + (x0 + c);
                    float xv = __ldg(xb + g);
                    float yv = __ldg(yb + g);
                    sxy[r * SP + c] = make_float2(xv + yv, xv - yv);
                }
                c += 4; r += 6;
                if (c >= IN_W) { c -= IN_W; r += 1; }
            }
        } else {
            #pragma unroll
            for (int it = 0; it < 7; it++) {
                if (r < IN_H) {
                    int gy = y0 + r, gx = x0 + c;
                    float sv = 0.0f, dv = 0.0f;
                    if (gy >= 0 && gy < IMG_H && gx >= 0 && gx < IMG_W) {
                        int g = gy * IMG_W + gx;
                        float xv = __ldg(xb + g);
                        float yv = __ldg(yb + g);
                        sv = xv + yv;
                        dv = xv - yv;
                    }
                    sxy[r * SP + c] = make_float2(sv, dv);
                }
                c += 4; r += 6;
                if (c >= IN_W) { c -= IN_W; r += 1; }
            }
        }
    }
    __syncthreads();

    // ---- Phase 2: horizontal pass, FUSED (single load stream, 4 maps) ----
    // 168 units of 8 output cols; each pin[i] loaded exactly once.
    // Store bank audit (STS.128, 8-lane wavefronts = consecutive rows):
    // bank group = 4*((33*row + col) mod 8) -> distinct over 8 rows.
    if (tid < IN_H * 4) {
        const int cg  = tid / IN_H;          // 0..3 (8-col groups)
        const int row = tid - cg * IN_H;     // 0..41
        const float2* pin = sxy + row * SP + cg * 8;
        float as[8], ad[8], as2[8], ad2[8];
        #pragma unroll
        for (int i = 0; i < 18; i++) {
            float2 v = pin[i];
            float ss = v.x * v.x;
            float dd = v.y * v.y;
            #pragma unroll
            for (int k = 0; k < 8; k++) {
                const int d = i - k;
                if (d == 0) {                 // first tap: mul-init (no MOV 0)
                    as[k]  = v.x * GW[0];
                    ad[k]  = v.y * GW[0];
                    as2[k] = ss  * GW[0];
                    ad2[k] = dd  * GW[0];
                } else if (d > 0 && d <= 10) {
                    const float w = GW[d];
                    as[k]  = fmaf(v.x, w, as[k]);
                    ad[k]  = fmaf(v.y, w, ad[k]);
                    as2[k] = fmaf(ss,  w, as2[k]);
                    ad2[k] = fmaf(dd,  w, ad2[k]);
                }
            }
        }
        const int hb = row * HP + cg * 8;
        #pragma unroll
        for (int k = 0; k < 8; k++)
            Hmap[hb + k] = make_float4(as[k], ad[k], as2[k], ad2[k]);
    }
    __syncthreads();

    // ---- Phase 3: vertical pass + SSIM, 4 rows per thread ----
    // Load bank audit (LDS.128): lane c -> word 4c, conflict-free per wavefront.
    const int c     = tid & 31;
    const int rbase = (tid >> 5) * 4;
    float ms[4], md[4], mss[4], mdd[4];
    const float4* p = Hmap + rbase * HP + c;
    #pragma unroll
    for (int j = 0; j < 14; j++) {
        float4 h = p[j * HP];
        #pragma unroll
        for (int k = 0; k < 4; k++) {
            const int d = j - k;
            if (d == 0) {
                ms[k]  = h.x * GW[0];
                md[k]  = h.y * GW[0];
                mss[k] = h.z * GW[0];
                mdd[k] = h.w * GW[0];
            } else if (d > 0 && d <= 10) {
                const float w = GW[d];
                ms[k]  = fmaf(h.x, w, ms[k]);
                md[k]  = fmaf(h.y, w, md[k]);
                mss[k] = fmaf(h.z, w, mss[k]);
                mdd[k] = fmaf(h.w, w, mdd[k]);
            }
        }
    }

    // SSIM in sum/diff-native form:
    //   a = mus^2-mud^2 (=4 mux*muy)      b = mus^2+mud^2 (=2(mux^2+muy^2))
    //   e = Ess-Edd     (=4 E[xy])        f = Ess+Edd     (=2(E[x^2]+E[y^2]))
    float lsum = 0.0f;
    #pragma unroll
    for (int k = 0; k < 4; k++) {
        float mus = ms[k],  mud = md[k];
        float a = fmaf(mus, mus, -(mud * mud));
        float b = fmaf(mus, mus,  (mud * mud));
        float e = mss[k] - mdd[k];
        float f = mss[k] + mdd[k];
        float n   = fmaf(0.5f, a, C1V) * fmaf(0.5f, e - a, C2V);
        float den = fmaf(0.5f, b, C1V) * fmaf(0.5f, f - b, C2V) + EPSV;
        float v = fmaf(__fdividef(n, den), 0.5f, 0.5f);
        v = fminf(fmaxf(v, 0.0f), 1.0f);
        lsum += v;
    }

    // ---- Reduction: warp shuffle -> smem -> block -> atomic ----
    #pragma unroll
    for (int off = 16; off > 0; off >>= 1)
        lsum += __shfl_xor_sync(0xFFFFFFFFu, lsum, off);
    if ((tid & 31) == 0) red[tid >> 5] = lsum;
    __syncthreads();
    if (tid == 0) {
        float t = 0.0f;
        #pragma unroll
        for (int w = 0; w < 8; w++) t += red[w];
        atomicAdd(out, t * inv_n);
    }
}

extern "C" void kernel_launch(void* const* d_in, const int* in_sizes, int n_in,
                              void* d_out, int out_size)
{
    const float* x = (const float*)d_in[0];
    const float* y = (const float*)d_in[1];
    float* out = (float*)d_out;

    zero_out_kernel<<<1, 1>>>(out);

    dim3 grid(IMG_W / TX, IMG_H / TY, 16 * 3);   // 16 x 16 x 48
    const float inv_n = 1.0f / (float)(16 * 3 * IMG_H * IMG_W);
    ssim_kernel<<<grid, NT>>>(x, y, out, inv_n);
}